// round 14
// baseline (speedup 1.0000x reference)
#include <cuda_runtime.h>
#include <cuda_bf16.h>
#include <cstdint>

#define D 512
#define HEADS 8
#define HD 64
#define TSEQ 1024
#define CHUNK 64
#define NC (TSEQ / CHUNK)   // 16
#define MAXB 4

// ---------------- scratch (no allocations allowed) ----------------
__device__ float g_ckv[MAXB * HEADS * NC * HD * HD];
__device__ float g_cks[MAXB * HEADS * NC * HD];
// bf16 split operands
__device__ __nv_bfloat16 g_whi[4 * D * D];
__device__ __nv_bfloat16 g_wlo[4 * D * D];
__device__ __nv_bfloat16 g_xhi[MAXB * TSEQ * D];
__device__ __nv_bfloat16 g_xlo[MAXB * TSEQ * D];
__device__ __nv_bfloat16 g_qhi[MAXB * TSEQ * D];
__device__ __nv_bfloat16 g_qlo[MAXB * TSEQ * D];
__device__ __nv_bfloat16 g_khi[MAXB * TSEQ * D];
__device__ __nv_bfloat16 g_klo[MAXB * TSEQ * D];
__device__ __nv_bfloat16 g_vhi[MAXB * TSEQ * D];
__device__ __nv_bfloat16 g_vlo[MAXB * TSEQ * D];
__device__ __nv_bfloat16 g_phi[MAXB * TSEQ * D];   // post-attention activations
__device__ __nv_bfloat16 g_plo[MAXB * TSEQ * D];

// ---------------- helpers ----------------
__device__ __forceinline__ void split2(float f, uint16_t& h, uint16_t& l) {
    __nv_bfloat16 hb = __float2bfloat16_rn(f);
    float hf = __bfloat162float(hb);
    __nv_bfloat16 lb = __float2bfloat16_rn(f - hf);
    h = __bfloat16_as_ushort(hb);
    l = __bfloat16_as_ushort(lb);
}
__device__ __forceinline__ float bf2f(uint16_t u) {
    return __bfloat162float(__ushort_as_bfloat16(u));
}

__device__ __forceinline__ void mma_bf16(float* d, const uint32_t* a, const uint32_t* b) {
    asm volatile(
        "mma.sync.aligned.m16n8k16.row.col.f32.bf16.bf16.f32 "
        "{%0,%1,%2,%3}, {%4,%5,%6,%7}, {%8,%9}, {%0,%1,%2,%3};"
        : "+f"(d[0]), "+f"(d[1]), "+f"(d[2]), "+f"(d[3])
        : "r"(a[0]), "r"(a[1]), "r"(a[2]), "r"(a[3]), "r"(b[0]), "r"(b[1]));
}

__device__ __forceinline__ uint32_t smem_u32(const void* p) {
    uint32_t a;
    asm("{ .reg .u64 t; cvta.to.shared.u64 t, %1; cvt.u32.u64 %0, t; }"
        : "=r"(a) : "l"(p));
    return a;
}
__device__ __forceinline__ void cp16(uint32_t dst, const void* src) {
    asm volatile("cp.async.cg.shared.global [%0], [%1], 16;"
                 :: "r"(dst), "l"(src));
}
#define CP_COMMIT() asm volatile("cp.async.commit_group;" ::: "memory")
#define CP_WAIT(n)  asm volatile("cp.async.wait_group %0;" :: "n"(n) : "memory")

#define LDSM4(r, addr) \
    asm volatile("ldmatrix.sync.aligned.m8n8.x4.shared.b16 {%0,%1,%2,%3}, [%4];" \
        : "=r"((r)[0]), "=r"((r)[1]), "=r"((r)[2]), "=r"((r)[3]) : "r"(addr))

// ---------------- merged conversion kernel (weights + x) ----------------
#define W4 (4 * D * D / 4)      // 262144 float4s of weights
__global__ void __launch_bounds__(256) convert_all(
    const float* __restrict__ x,
    const float* __restrict__ Wq, const float* __restrict__ Wk,
    const float* __restrict__ Wv, const float* __restrict__ Wo, int n4x)
{
    int gid = blockIdx.x * 256 + threadIdx.x;
    if (gid < W4) {
        int w = gid >> 16;
        int off = gid & 65535;
        const float* src = (w == 0) ? Wq : (w == 1) ? Wk : (w == 2) ? Wv : Wo;
        float4 v = ((const float4*)src)[off];
        float f[4] = {v.x, v.y, v.z, v.w};
        uint16_t h[4], l[4];
#pragma unroll
        for (int j = 0; j < 4; ++j) split2(f[j], h[j], l[j]);
        ((uint2*)(g_whi + (size_t)w * D * D))[off] =
            make_uint2((uint32_t)h[0] | ((uint32_t)h[1] << 16),
                       (uint32_t)h[2] | ((uint32_t)h[3] << 16));
        ((uint2*)(g_wlo + (size_t)w * D * D))[off] =
            make_uint2((uint32_t)l[0] | ((uint32_t)l[1] << 16),
                       (uint32_t)l[2] | ((uint32_t)l[3] << 16));
    } else {
        int i = gid - W4;
        if (i < n4x) {
            float4 v = ((const float4*)x)[i];
            float f[4] = {v.x, v.y, v.z, v.w};
            uint16_t h[4], l[4];
#pragma unroll
            for (int j = 0; j < 4; ++j) split2(f[j], h[j], l[j]);
            ((uint2*)g_xhi)[i] = make_uint2((uint32_t)h[0] | ((uint32_t)h[1] << 16),
                                            (uint32_t)h[2] | ((uint32_t)h[3] << 16));
            ((uint2*)g_xlo)[i] = make_uint2((uint32_t)l[0] | ((uint32_t)l[1] << 16),
                                            (uint32_t)l[2] | ((uint32_t)l[3] << 16));
        }
    }
}

// ---------------- mma.sync split-bf16 GEMM (tile 128x64, 2 CTAs/SM) ----------------
#define ROWU 36
#define ARRUA (128 * ROWU)     // 4608
#define ARRUB (64 * ROWU)      // 2304
#define BUFU (2 * ARRUA + 2 * ARRUB)   // 13824
#define GEMM_SMEM (2 * BUFU * 4)       // 110592 bytes

__device__ __forceinline__ void load_chunk_async(
    uint32_t sbB, const uint32_t* Ahi, const uint32_t* Alo,
    const uint32_t* Bhi, const uint32_t* Blo,
    int rowBase, int colBase, int k0u, int tid)
{
#pragma unroll
    for (int it = 0; it < 4; ++it) {
        int lin = tid + it * 256;          // 0..1023
        int r = lin >> 3, q = lin & 7;
        uint32_t dOff = (uint32_t)(r * ROWU + q * 4) * 4;
        cp16(sbB + dOff, Ahi + (size_t)(rowBase + r) * 256 + k0u + q * 4);
        cp16(sbB + ARRUA * 4 + dOff, Alo + (size_t)(rowBase + r) * 256 + k0u + q * 4);
    }
#pragma unroll
    for (int it = 0; it < 2; ++it) {
        int lin = tid + it * 256;          // 0..511
        int r = lin >> 3, q = lin & 7;
        uint32_t dOff = (uint32_t)(r * ROWU + q * 4) * 4;
        cp16(sbB + 2 * ARRUA * 4 + dOff, Bhi + (size_t)(colBase + r) * 256 + k0u + q * 4);
        cp16(sbB + (2 * ARRUA + ARRUB) * 4 + dOff,
             Blo + (size_t)(colBase + r) * 256 + k0u + q * 4);
    }
}

__global__ void __launch_bounds__(256, 2) mma_gemm(
    int asel, int wBase, int oselBase,
    const float* __restrict__ bias0, const float* __restrict__ bias1,
    const float* __restrict__ bias2,
    float* __restrict__ Oext, int actmask)
{
    extern __shared__ __align__(16) uint32_t smu[];
    int tid = threadIdx.x, lane = tid & 31, wid = tid >> 5;
    int warpRow = wid >> 2;    // 0..1 (64 rows each)
    int warpCol = wid & 3;     // 0..3 (16 cols each)
    int z = blockIdx.z;
    int rowBase = blockIdx.y * 128;
    int colBase = blockIdx.x * 64;

    const uint32_t* Ahi = asel ? (const uint32_t*)g_phi : (const uint32_t*)g_xhi;
    const uint32_t* Alo = asel ? (const uint32_t*)g_plo : (const uint32_t*)g_xlo;
    int wz = wBase + z;
    const uint32_t* Bhi = (const uint32_t*)g_whi + (size_t)wz * (D * D / 2);
    const uint32_t* Blo = (const uint32_t*)g_wlo + (size_t)wz * (D * D / 2);
    const float* bias = (z == 0) ? bias0 : (z == 1) ? bias1 : bias2;
    int osel = oselBase + z;
    __nv_bfloat16* Ohi = (osel == 0) ? g_qhi : (osel == 1) ? g_khi : g_vhi;
    __nv_bfloat16* Olo = (osel == 0) ? g_qlo : (osel == 1) ? g_klo : g_vlo;
    int act = (actmask >> z) & 1;

    uint32_t sbB = smem_u32(smu);

    int lrA = lane & 15, lhA = lane >> 4;
    int brB = ((lane >> 4) << 3) + (lane & 7);
    int bhB = (lane >> 3) & 1;

    float acc[4][2][4];
#pragma unroll
    for (int mt = 0; mt < 4; ++mt)
#pragma unroll
        for (int nt = 0; nt < 2; ++nt)
#pragma unroll
            for (int r = 0; r < 4; ++r) acc[mt][nt][r] = 0.f;

    load_chunk_async(sbB, Ahi, Alo, Bhi, Blo, rowBase, colBase, 0, tid);
    CP_COMMIT();

    for (int c = 0; c < 8; ++c) {
        int buf = c & 1;
        if (c < 7) {
            load_chunk_async(sbB + ((c + 1) & 1) * BUFU * 4,
                             Ahi, Alo, Bhi, Blo, rowBase, colBase,
                             (c + 1) * 32, tid);
            CP_COMMIT();
            CP_WAIT(1);
        } else {
            CP_WAIT(0);
        }
        __syncthreads();

        uint32_t aBH = sbB + (uint32_t)buf * BUFU * 4;
        uint32_t aBL = aBH + ARRUA * 4;
        uint32_t bBH = aBH + 2 * ARRUA * 4;
        uint32_t bBL = aBH + (2 * ARRUA + ARRUB) * 4;
#pragma unroll
        for (int ks = 0; ks < 4; ++ks) {
            uint32_t ahi[4][4], alo[4][4];
#pragma unroll
            for (int mt = 0; mt < 4; ++mt) {
                uint32_t off = (uint32_t)((warpRow * 64 + mt * 16 + lrA) * ROWU
                                          + ks * 8 + lhA * 4) * 4;
                LDSM4(ahi[mt], aBH + off);
                LDSM4(alo[mt], aBL + off);
            }
            uint32_t off = (uint32_t)((warpCol * 16 + brB) * ROWU
                                      + ks * 8 + bhB * 4) * 4;
            uint32_t t0[4], t1[4];
            LDSM4(t0, bBH + off);
            LDSM4(t1, bBL + off);
#pragma unroll
            for (int mt = 0; mt < 4; ++mt)
#pragma unroll
                for (int q = 0; q < 2; ++q) {
                    mma_bf16(acc[mt][q], ahi[mt], &t0[2 * q]);
                    mma_bf16(acc[mt][q], ahi[mt], &t1[2 * q]);
                    mma_bf16(acc[mt][q], alo[mt], &t0[2 * q]);
                }
        }
        __syncthreads();
    }

#pragma unroll
    for (int mt = 0; mt < 4; ++mt) {
        int r0 = rowBase + warpRow * 64 + mt * 16 + (lane >> 2);
#pragma unroll
        for (int nt = 0; nt < 2; ++nt) {
            int cc = colBase + warpCol * 16 + nt * 8 + (lane & 3) * 2;
            float b0 = bias[cc], b1 = bias[cc + 1];
            float v0 = acc[mt][nt][0] + b0;
            float v1 = acc[mt][nt][1] + b1;
            float v2 = acc[mt][nt][2] + b0;
            float v3 = acc[mt][nt][3] + b1;
            if (act) {
                v0 = (v0 > 0.f) ? v0 + 1.f : __expf(v0);
                v1 = (v1 > 0.f) ? v1 + 1.f : __expf(v1);
                v2 = (v2 > 0.f) ? v2 + 1.f : __expf(v2);
                v3 = (v3 > 0.f) ? v3 + 1.f : __expf(v3);
            }
            if (osel == 3) {
                *(float2*)&Oext[(size_t)r0 * D + cc] = make_float2(v0, v1);
                *(float2*)&Oext[(size_t)(r0 + 8) * D + cc] = make_float2(v2, v3);
            } else {
                uint16_t h0, l0, h1, l1;
                split2(v0, h0, l0); split2(v1, h1, l1);
                *(uint32_t*)&Ohi[(size_t)r0 * D + cc] = (uint32_t)h0 | ((uint32_t)h1 << 16);
                *(uint32_t*)&Olo[(size_t)r0 * D + cc] = (uint32_t)l0 | ((uint32_t)l1 << 16);
                split2(v2, h0, l0); split2(v3, h1, l1);
                *(uint32_t*)&Ohi[(size_t)(r0 + 8) * D + cc] = (uint32_t)h0 | ((uint32_t)h1 << 16);
                *(uint32_t*)&Olo[(size_t)(r0 + 8) * D + cc] = (uint32_t)l0 | ((uint32_t)l1 << 16);
            }
        }
    }
}

// ---------------- per-chunk local sums (CHUNK=64, m-split x2, bf16 src) ----------------
__global__ void __launch_bounds__(256) chunk_sum_kernel()
{
    int bc = blockIdx.x;            // b*NC + c
    int hm = blockIdx.y;
    int h = hm >> 1, mh = hm & 1;
    int b = bc / NC, c = bc % NC;
    extern __shared__ __align__(16) float smf[];
    float* ks = smf;                   // [CHUNK][HD]
    float* vs = smf + CHUNK * HD;      // [CHUNK][32]

    int tid = threadIdx.x;
    size_t nbase = (size_t)b * TSEQ + (size_t)c * CHUNK;
    const uint32_t* kh = (const uint32_t*)g_khi;
    const uint32_t* kl = (const uint32_t*)g_klo;
    const uint32_t* vh = (const uint32_t*)g_vhi;
    const uint32_t* vl = (const uint32_t*)g_vlo;

#pragma unroll
    for (int it = 0; it < 4; it++) {
        int lin = tid + it * 256;      // 1024 groups of 4 floats
        int t = lin >> 4;
        int d4 = lin & 15;
        size_t e2 = ((nbase + t) * D + h * HD + d4 * 4) >> 1;   // u32 index
        uint2 ah = *(const uint2*)&kh[e2];
        uint2 al = *(const uint2*)&kl[e2];
        float4 kv;
        kv.x = bf2f((uint16_t)ah.x) + bf2f((uint16_t)al.x);
        kv.y = bf2f((uint16_t)(ah.x >> 16)) + bf2f((uint16_t)(al.x >> 16));
        kv.z = bf2f((uint16_t)ah.y) + bf2f((uint16_t)al.y);
        kv.w = bf2f((uint16_t)(ah.y >> 16)) + bf2f((uint16_t)(al.y >> 16));
        ((float4*)ks)[lin] = kv;
    }
#pragma unroll
    for (int it = 0; it < 2; it++) {
        int lin = tid + it * 256;      // 512 groups of 4
        int t = lin >> 3;
        int m4 = lin & 7;
        size_t e2 = ((nbase + t) * D + h * HD + mh * 32 + m4 * 4) >> 1;
        uint2 ah = *(const uint2*)&vh[e2];
        uint2 al = *(const uint2*)&vl[e2];
        float4 vv;
        vv.x = bf2f((uint16_t)ah.x) + bf2f((uint16_t)al.x);
        vv.y = bf2f((uint16_t)(ah.x >> 16)) + bf2f((uint16_t)(al.x >> 16));
        vv.z = bf2f((uint16_t)ah.y) + bf2f((uint16_t)al.y);
        vv.w = bf2f((uint16_t)(ah.y >> 16)) + bf2f((uint16_t)(al.y >> 16));
        ((float4*)vs)[lin] = vv;
    }
    __syncthreads();

    int d0 = (tid >> 4) * 4;
    int m0 = (tid & 15) * 2;
    float acc[4][2];
#pragma unroll
    for (int i = 0; i < 4; i++) { acc[i][0] = 0.f; acc[i][1] = 0.f; }

#pragma unroll 8
    for (int t = 0; t < CHUNK; t++) {
        float4 kd = *(const float4*)&ks[t * HD + d0];
        float2 vm = *(const float2*)&vs[t * 32 + m0];
        float ka[4] = {kd.x, kd.y, kd.z, kd.w};
#pragma unroll
        for (int i = 0; i < 4; i++) {
            acc[i][0] += ka[i] * vm.x;
            acc[i][1] += ka[i] * vm.y;
        }
    }

    size_t sidx = ((size_t)(b * HEADS + h) * NC + c);
    float* ckv = g_ckv + sidx * HD * HD;
#pragma unroll
    for (int i = 0; i < 4; i++)
        *(float2*)&ckv[(d0 + i) * HD + mh * 32 + m0] = make_float2(acc[i][0], acc[i][1]);

    if (mh == 0 && tid < HD) {
        float s = 0.f;
#pragma unroll 8
        for (int t = 0; t < CHUNK; t++) s += ks[t * HD + tid];
        g_cks[sidx * HD + tid] = s;
    }
}
#define CS_SMEM ((CHUNK * HD + CHUNK * 32) * 4)   // 24576 B

// ---------------- exclusive prefix over chunks per (b,h), float4/thread ----------------
__global__ void __launch_bounds__(256) prefix_kernel()
{
    int bh = blockIdx.x;
    int e4 = blockIdx.y * 256 + threadIdx.x;   // 0..1023 float4 index
    float4* base = (float4*)(g_ckv + (size_t)bh * NC * HD * HD) + e4;

    float4 v[NC];
#pragma unroll
    for (int c = 0; c < NC; c++) v[c] = base[c * (HD * HD / 4)];
    float4 carry = make_float4(0.f, 0.f, 0.f, 0.f);
#pragma unroll
    for (int c = 0; c < NC; c++) {
        float4 t = v[c];
        base[c * (HD * HD / 4)] = carry;
        carry.x += t.x; carry.y += t.y; carry.z += t.z; carry.w += t.w;
    }

    if (blockIdx.y == 0 && threadIdx.x < HD) {
        float* kb = g_cks + (size_t)bh * NC * HD + threadIdx.x;
        float w[NC];
#pragma unroll
        for (int c = 0; c < NC; c++) w[c] = kb[c * HD];
        float kc = 0.f;
#pragma unroll
        for (int c = 0; c < NC; c++) {
            float t = w[c];
            kb[c * HD] = kc;
            kc += t;
        }
    }
}

// ---------------- tensor-core per-chunk attention (CHUNK=64) ----------------
#define QHI_O 0
#define QLO_O 2304
#define KHI_O 4608
#define KLO_O 6912
#define VTHI_O 9216
#define VTLO_O 11520
#define PTHI_O 13824
#define PTLO_O 16128
#define SHI_O 18432
#define SLO_O 20736
#define KSUM_O 23040
#define DNS_O 23104
#define DNV_O 23232
#define ATTN_U32 23296
#define ATTN_SMEM (ATTN_U32 * 4)   // 93184 B -> 2 CTAs/SM

__global__ void __launch_bounds__(256) attn_chunk_kernel()
{
    int bc = blockIdx.x;
    int h = blockIdx.y;
    int b = bc / NC, c = bc % NC;
    extern __shared__ __align__(16) uint32_t smu[];
    uint16_t* sh = (uint16_t*)smu;
    float* ksum = (float*)(smu + KSUM_O);
    float* dnS = (float*)(smu + DNS_O);
    float* dnv = (float*)(smu + DNV_O);

    int tid = threadIdx.x, lane = tid & 31, wid = tid >> 5;
    size_t nbase = (size_t)b * TSEQ + (size_t)c * CHUNK;
    size_t sidx = ((size_t)(b * HEADS + h) * NC + c);
    uint32_t sbB = smem_u32(smu);

    // ---- Q/K hi+lo: direct cp.async copies (row-major, stride-36 dst) ----
#pragma unroll
    for (int it = 0; it < 2; ++it) {
        int lin = tid + it * 256;      // 0..511: row i = lin>>3, 16B chunk q = lin&7
        int i = lin >> 3, q = lin & 7;
        const char* srcQh = (const char*)&g_qhi[(nbase + i) * D + h * HD] + q * 16;
        const char* srcQl = (const char*)&g_qlo[(nbase + i) * D + h * HD] + q * 16;
        const char* srcKh = (const char*)&g_khi[(nbase + i) * D + h * HD] + q * 16;
        const char* srcKl = (const char*)&g_klo[(nbase + i) * D + h * HD] + q * 16;
        uint32_t dOff = (uint32_t)(i * 144 + q * 16);
        cp16(sbB + QHI_O * 4 + dOff, srcQh);
        cp16(sbB + QLO_O * 4 + dOff, srcQl);
        cp16(sbB + KHI_O * 4 + dOff, srcKh);
        cp16(sbB + KLO_O * 4 + dOff, srcKl);
    }
    CP_COMMIT();

    // ---- V^T from pre-split bf16 (transpose u32 -> two b16 stores) ----
    const uint32_t* vh = (const uint32_t*)g_vhi;
    const uint32_t* vl = (const uint32_t*)g_vlo;
#pragma unroll
    for (int it = 0; it < 8; ++it) {
        int lin = tid + it * 256;      // 0..2047: row i = lin>>5, pair p = lin&31
        int i = lin >> 5, p = lin & 31, d = p * 2;
        size_t e2 = ((nbase + i) * D + h * HD) / 2 + p;
        uint32_t ah = vh[e2], al = vl[e2];
        sh[VTHI_O * 2 + d * 72 + i] = (uint16_t)ah;
        sh[VTHI_O * 2 + (d + 1) * 72 + i] = (uint16_t)(ah >> 16);
        sh[VTLO_O * 2 + d * 72 + i] = (uint16_t)al;
        sh[VTLO_O * 2 + (d + 1) * 72 + i] = (uint16_t)(al >> 16);
    }
    // ---- KVp^T: fp32 -> split2 (only remaining conversion) ----
#pragma unroll
    for (int it = 0; it < 16; ++it) {
        int e = tid + it * 256;        // e = d*64+m
        float pv = g_ckv[sidx * (HD * HD) + e];
        uint16_t hh, ll;
        split2(pv, hh, ll);
        sh[PTHI_O * 2 + (e & 63) * 72 + (e >> 6)] = hh;
        sh[PTLO_O * 2 + (e & 63) * 72 + (e >> 6)] = ll;
    }
    if (tid < HD) ksum[tid] = g_cks[sidx * HD + tid];
    CP_WAIT(0);
    __syncthreads();

    int wr = wid >> 1, wc = wid & 1;
    int r0 = wr * 16, c0 = wc * 32;
    int lrA = lane & 15, lhA = lane >> 4;
    int brB = ((lane >> 4) << 3) + (lane & 7);
    int bhB = (lane >> 3) & 1;
    int ra = r0 + (lane >> 2), rb = ra + 8;

    // ---- stage 1: S = Q K^T (split mma), mask, rowsum, split-store ----
    {
        float s1[4][4];
#pragma unroll
        for (int nt = 0; nt < 4; ++nt)
#pragma unroll
            for (int r = 0; r < 4; ++r) s1[nt][r] = 0.f;

#pragma unroll
        for (int ksx = 0; ksx < 4; ++ksx) {
            uint32_t ahi[4], alo[4];
            uint32_t aoff = (uint32_t)((r0 + lrA) * 36 + ksx * 8 + lhA * 4) * 4;
            LDSM4(ahi, sbB + QHI_O * 4 + aoff);
            LDSM4(alo, sbB + QLO_O * 4 + aoff);
#pragma unroll
            for (int p = 0; p < 2; ++p) {
                uint32_t boff = (uint32_t)((c0 + p * 16 + brB) * 36 + ksx * 8 + bhB * 4) * 4;
                uint32_t t0[4], t1[4];
                LDSM4(t0, sbB + KHI_O * 4 + boff);
                LDSM4(t1, sbB + KLO_O * 4 + boff);
#pragma unroll
                for (int q = 0; q < 2; ++q) {
                    mma_bf16(s1[2 * p + q], ahi, &t0[2 * q]);
                    mma_bf16(s1[2 * p + q], ahi, &t1[2 * q]);
                    mma_bf16(s1[2 * p + q], alo, &t0[2 * q]);
                }
            }
        }
        float rsa = 0.f, rsb = 0.f;
#pragma unroll
        for (int nt = 0; nt < 4; ++nt) {
            int ca = c0 + nt * 8 + 2 * (lane & 3);
            float v0 = (ca <= ra) ? s1[nt][0] : 0.f;
            float v1 = (ca + 1 <= ra) ? s1[nt][1] : 0.f;
            float v2 = (ca <= rb) ? s1[nt][2] : 0.f;
            float v3 = (ca + 1 <= rb) ? s1[nt][3] : 0.f;
            rsa += v0 + v1;
            rsb += v2 + v3;
            uint16_t h0, l0, h1, l1;
            split2(v0, h0, l0); split2(v1, h1, l1);
            smu[SHI_O + ra * 36 + (ca >> 1)] = (uint32_t)h0 | ((uint32_t)h1 << 16);
            smu[SLO_O + ra * 36 + (ca >> 1)] = (uint32_t)l0 | ((uint32_t)l1 << 16);
            split2(v2, h0, l0); split2(v3, h1, l1);
            smu[SHI_O + rb * 36 + (ca >> 1)] = (uint32_t)h0 | ((uint32_t)h1 << 16);
            smu[SLO_O + rb * 36 + (ca >> 1)] = (uint32_t)l0 | ((uint32_t)l1 << 16);
        }
        rsa += __shfl_xor_sync(0xffffffff, rsa, 1);
        rsa += __shfl_xor_sync(0xffffffff, rsa, 2);
        rsb += __shfl_xor_sync(0xffffffff, rsb, 1);
        rsb += __shfl_xor_sync(0xffffffff, rsb, 2);
        if ((lane & 3) == 0) {
            dnS[ra * 2 + wc] = rsa;
            dnS[rb * 2 + wc] = rsb;
        }
    }
    __syncthreads();

    // ---- stage 2: out = S V + Q KVp (one accumulator chain) ----
    float s2[4][4];
#pragma unroll
    for (int nt = 0; nt < 4; ++nt)
#pragma unroll
        for (int r = 0; r < 4; ++r) s2[nt][r] = 0.f;

#pragma unroll
    for (int ksx = 0; ksx < 4; ++ksx) {     // S * V  (k = j)
        uint32_t ahi[4], alo[4];
        uint32_t aoff = (uint32_t)((r0 + lrA) * 36 + ksx * 8 + lhA * 4) * 4;
        LDSM4(ahi, sbB + SHI_O * 4 + aoff);
        LDSM4(alo, sbB + SLO_O * 4 + aoff);
#pragma unroll
        for (int p = 0; p < 2; ++p) {
            uint32_t boff = (uint32_t)((c0 + p * 16 + brB) * 36 + ksx * 8 + bhB * 4) * 4;
            uint32_t t0[4], t1[4];
            LDSM4(t0, sbB + VTHI_O * 4 + boff);
            LDSM4(t1, sbB + VTLO_O * 4 + boff);
#pragma unroll
            for (int q = 0; q < 2; ++q) {
                mma_bf16(s2[2 * p + q], ahi, &t0[2 * q]);
                mma_bf16(s2[2 * p + q], ahi, &t1[2 * q]);
                mma_bf16(s2[2 * p + q], alo, &t0[2 * q]);
            }
        }
    }
#pragma unroll
    for (int ksx = 0; ksx < 4; ++ksx) {     // Q * KVp  (k = d)
        uint32_t ahi[4], alo[4];
        uint32_t aoff = (uint32_t)((r0 + lrA) * 36 + ksx * 8 + lhA * 4) * 4;
        LDSM4(ahi, sbB + QHI_O * 4 + aoff);
        LDSM4(alo, sbB + QLO_O * 4 + aoff);
#pragma unroll
        for (int p = 0; p < 2; ++p) {
            uint32_t boff = (uint32_t)((c0 + p * 16 + brB) * 36 + ksx * 8 + bhB * 4) * 4;
            uint32_t t0[4], t1[4];
            LDSM4(t0, sbB + PTHI_O * 4 + boff);
            LDSM4(t1, sbB + PTLO_O * 4 + boff);
#pragma unroll
            for (int q = 0; q < 2; ++q) {
                mma_bf16(s2[2 * p + q], ahi, &t0[2 * q]);
                mma_bf16(s2[2 * p + q], ahi, &t1[2 * q]);
                mma_bf16(s2[2 * p + q], alo, &t0[2 * q]);
            }
        }
    }

    // ---- denom: rowsum(maskS) + Q . ksum ----
    if (tid < 64) {
        float s = dnS[tid * 2] + dnS[tid * 2 + 1];
#pragma unroll 8
        for (int d = 0; d < HD; ++d) {
            float qv = bf2f(sh[QHI_O * 2 + tid * 72 + d]) +
                       bf2f(sh[QLO_O * 2 + tid * 72 + d]);
            s += qv * ksum[d];
        }
        dnv[tid] = 1.f / fmaxf(s, 1e-6f);
    }
    __syncthreads();

    // ---- epilogue: scale + split-store ----
    float ia = dnv[ra], ib = dnv[rb];
#pragma unroll
    for (int nt = 0; nt < 4; ++nt) {
        int ca = c0 + nt * 8 + 2 * (lane & 3);
        float o0 = s2[nt][0] * ia;
        float o1 = s2[nt][1] * ia;
        float o2 = s2[nt][2] * ib;
        float o3 = s2[nt][3] * ib;
        uint16_t h0, l0, h1, l1;
        size_t ga = (nbase + ra) * D + h * HD + ca;
        size_t gb = (nbase + rb) * D + h * HD + ca;
        split2(o0, h0, l0); split2(o1, h1, l1);
        *(uint32_t*)&g_phi[ga] = (uint32_t)h0 | ((uint32_t)h1 << 16);
        *(uint32_t*)&g_plo[ga] = (uint32_t)l0 | ((uint32_t)l1 << 16);
        split2(o2, h0, l0); split2(o3, h1, l1);
        *(uint32_t*)&g_phi[gb] = (uint32_t)h0 | ((uint32_t)h1 << 16);
        *(uint32_t*)&g_plo[gb] = (uint32_t)l0 | ((uint32_t)l1 << 16);
    }
}

// ---------------- launch ----------------
extern "C" void kernel_launch(void* const* d_in, const int* in_sizes, int n_in,
                              void* d_out, int out_size)
{
    const float* x  = (const float*)d_in[0];
    const float* Wq = (const float*)d_in[1];
    const float* bq = (const float*)d_in[2];
    const float* Wk = (const float*)d_in[3];
    const float* bk = (const float*)d_in[4];
    const float* Wv = (const float*)d_in[5];
    const float* bv = (const float*)d_in[6];
    const float* Wo = (const float*)d_in[7];
    const float* bo = (const float*)d_in[8];

    int N = in_sizes[0] / D;     // b * t
    int B = N / TSEQ;
    int rowTiles = N / 128;
    int n4x = N * D / 4;

    cudaFuncSetAttribute(mma_gemm,
                         cudaFuncAttributeMaxDynamicSharedMemorySize, GEMM_SMEM);
    cudaFuncSetAttribute(attn_chunk_kernel,
                         cudaFuncAttributeMaxDynamicSharedMemorySize, ATTN_SMEM);

    // merged split conversion: weights + x
    convert_all<<<(W4 + n4x + 255) / 256, 256>>>(x, Wq, Wk, Wv, Wo, n4x);

    // fused QKV projection (z = 0,1,2 -> q,k,v); elu+1 on q,k
    dim3 gq(D / 64, rowTiles, 3);
    mma_gemm<<<gq, 256, GEMM_SMEM>>>(0, 0, 0, bq, bk, bv, nullptr, 0x3);

    chunk_sum_kernel<<<dim3(B * NC, HEADS * 2), 256, CS_SMEM>>>();
    prefix_kernel<<<dim3(B * HEADS, 4), 256>>>();
    attn_chunk_kernel<<<dim3(B * NC, HEADS), 256, ATTN_SMEM>>>();

    // output projection from split attention output -> d_out
    dim3 go(D / 64, rowTiles, 1);
    mma_gemm<<<go, 256, GEMM_SMEM>>>(1, 3, 3, bo, bo, bo, (float*)d_out, 0x0);
}